// round 17
// baseline (speedup 1.0000x reference)
#include <cuda_runtime.h>
#include <cuda_bf16.h>
#include <cstdint>

// GradientLayerPoisson: tanh-MLP 2->256->256->256->1 second-order jet
// via mma.sync bf16 3-term split GEMMs (hh + hl + lh), fully fused.
// R16: 256 thr/CTA (8 warps, n=32/warp), 16 samples/CTA, 2 CTAs/SM.
// A-fragment-ordered H planes (1 LDS.128 per MMA A operand), fragment-ordered
// B image in global. Halved per-thread seed/epilogue vs R15.

#define HID  256

// SMEM byte offsets
#define SM_AH   0        // 3 st x 16 steps x 32 lanes x 16B = 24576
#define SM_AL   24576    // same
#define SM_BIAS 49152    // [2][256] fp32
#define SM_W4   51200    // [256] fp32
#define SM_X    52224    // [16] float2
#define SM_OUT  52352    // [3][16] fp32
#define SM_TOT  52544

// fragment-ordered weight image: [l][step][wq][ntg][lane] uint4 = {Bh0,Bh1,Bl0,Bl1}
__device__ __align__(16) uint4 g_Wq[2 * 16 * 4 * 8 * 32];

__device__ __forceinline__ void tanh_d(float x, float& a, float& s2) {
    x = fminf(fmaxf(x, -15.f), 15.f);
    float t = exp2f(x * 2.8853900817779268f);
    float d = 1.f + t, r;
    asm("rcp.approx.ftz.f32 %0, %1;" : "=f"(r) : "f"(d));
    r = r * (2.f - d * r);
    a  = 1.f - 2.f * r;
    s2 = 4.f * r * (1.f - r);
}

// pack (x,y) -> hi word {bf16(x) lo-half, bf16(y) hi-half} and residual lo word
__device__ __forceinline__ void pk2(float x, float y, uint32_t& hi, uint32_t& lo) {
    uint32_t h;
    asm("cvt.rn.bf16x2.f32 %0, %1, %2;" : "=r"(h) : "f"(y), "f"(x));
    float fx = __uint_as_float(h << 16);
    float fy = __uint_as_float(h & 0xffff0000u);
    uint32_t l_;
    asm("cvt.rn.bf16x2.f32 %0, %1, %2;" : "=r"(l_) : "f"(y - fy), "f"(x - fx));
    hi = h; lo = l_;
}

#define MMA(Dx, A0, A1, A2, A3, B0, B1)                                         \
    asm volatile("mma.sync.aligned.m16n8k16.row.col.f32.bf16.bf16.f32 "         \
                 "{%0,%1,%2,%3},{%4,%5,%6,%7},{%8,%9},{%0,%1,%2,%3};"           \
                 : "+f"((Dx)[0]), "+f"((Dx)[1]), "+f"((Dx)[2]), "+f"((Dx)[3])   \
                 : "r"(A0), "r"(A1), "r"(A2), "r"(A3), "r"(B0), "r"(B1))

// ---- prep: bake W2/W3 into fragment-ordered hi/lo image ----
extern "C" __global__ void prep_w(const float* __restrict__ W2,
                                  const float* __restrict__ W3) {
    const int b = blockIdx.x;                 // 32 blocks: l(2) x kc(4) x ks(4)
    const int l = b >> 4, kc = (b >> 2) & 3, ks = b & 3;
    const int step = kc * 4 + ks;
    const int t = threadIdx.x, wq = t >> 5, lane = t & 31;
    const int g4 = lane >> 2, tid3 = lane & 3;
    const float* W = l ? W3 : W2;
    #pragma unroll
    for (int nt = 0; nt < 8; ++nt) {
        int n = wq * 64 + nt * 8 + g4;
        int kpA = ks * 8 + tid3;       // j = 0
        int kpB = kpA + 4;             // j = 1
        uint32_t h0, l0, h1, l1;
        pk2(W[(kc * 64 + 2 * kpA) * HID + n], W[(kc * 64 + 2 * kpA + 1) * HID + n], h0, l0);
        pk2(W[(kc * 64 + 2 * kpB) * HID + n], W[(kc * 64 + 2 * kpB + 1) * HID + n], h1, l1);
        g_Wq[(((l * 16 + step) * 4 + wq) * 8 + nt) * 32 + lane] =
            make_uint4(h0, h1, l0, l1);
    }
}

extern "C" __global__ void __launch_bounds__(256, 2)
pinn_mma_kernel(const float* __restrict__ x,
                const float* __restrict__ W1, const float* __restrict__ b1,
                const float* __restrict__ b2, const float* __restrict__ b3,
                const float* __restrict__ W4, const float* __restrict__ b4,
                float* __restrict__ out, int B) {
    extern __shared__ unsigned char smem[];
    uint32_t* AH     = (uint32_t*)(smem + SM_AH);
    uint32_t* AL     = (uint32_t*)(smem + SM_AL);
    float*    biasSm = (float*)(smem + SM_BIAS);
    float*    w4Sm   = (float*)(smem + SM_W4);
    float2*   xSm    = (float2*)(smem + SM_X);
    float*    outSm  = (float*)(smem + SM_OUT);

    const int t = threadIdx.x, lane = t & 31, w = t >> 5;
    const int bs = blockIdx.x * 16;
    const int g4 = lane >> 2, tid3 = lane & 3;

    if (t < 48) outSm[t] = 0.f;
    if (t < 16) xSm[t] = ((const float2*)x)[bs + t];
    biasSm[t]       = b2[t];
    biasSm[256 + t] = b3[t];
    w4Sm[t]         = W4[t];
    __syncthreads();

    // ---- layer 1: jets into fragment-ordered A planes (z' = W1[0][u], z''=0) ----
    {
        const int up = t & 127, sh = t >> 7;  // unit pair, sample half
        const int step_t = up >> 3, o = up & 7;
        const int wsel = (o & 4) ? 2 : 0;
        float2 c0 = ((const float2*)W1)[up];
        float2 c1 = ((const float2*)(W1 + HID))[up];
        float2 bb = ((const float2*)b1)[up];
        #pragma unroll 4
        for (int i = 0; i < 8; ++i) {
            int s = sh * 8 + i;
            float2 xv = xSm[s];
            float a0, s20, a0b, s21;
            tanh_d(fmaf(xv.x, c0.x, fmaf(xv.y, c1.x, bb.x)), a0, s20);
            tanh_d(fmaf(xv.x, c0.y, fmaf(xv.y, c1.y, bb.y)), a0b, s21);
            float a1u0 = s20 * c0.x, a2u0 = -2.f * a0  * a1u0 * c0.x;
            float a1u1 = s21 * c0.y, a2u1 = -2.f * a0b * a1u1 * c0.y;
            const int lane_t = ((s & 7) << 2) | (o & 3);
            const int widx = wsel + sh;
            const int i0 = ((0 * 16 + step_t) * 32 + lane_t) * 4 + widx;
            const int i1 = ((1 * 16 + step_t) * 32 + lane_t) * 4 + widx;
            const int i2 = ((2 * 16 + step_t) * 32 + lane_t) * 4 + widx;
            uint32_t h, lo2;
            pk2(a0, a0b, h, lo2);    AH[i0] = h; AL[i0] = lo2;
            pk2(a1u0, a1u1, h, lo2); AH[i1] = h; AL[i1] = lo2;
            pk2(a2u0, a2u1, h, lo2); AH[i2] = h; AL[i2] = lo2;
        }
    }
    __syncthreads();

    float D[3][4][4];
    float ps[2][3];

    const uint4* AHq = (const uint4*)(smem + SM_AH) + lane;  // + (st*16+step)*32
    const uint4* ALq = (const uint4*)(smem + SM_AL) + lane;

    #pragma unroll 1
    for (int l = 0; l < 2; ++l) {
        #pragma unroll
        for (int a = 0; a < 3; ++a)
            #pragma unroll
            for (int c = 0; c < 4; ++c)
                #pragma unroll
                for (int d = 0; d < 4; ++d) D[a][c][d] = 0.f;

        // warp w covers quadrant wq = w>>1, n-tile group (w&1)*4 .. +4
        const uint4* wpT = g_Wq + (((l * 16) * 4 + (w >> 1)) * 8 + (w & 1) * 4) * 32 + lane;

        #pragma unroll
        for (int step = 0; step < 16; ++step) {
            uint4 qb[4];
            #pragma unroll
            for (int nt = 0; nt < 4; ++nt)
                qb[nt] = wpT[step * 1024 + nt * 32];
            #pragma unroll
            for (int st = 0; st < 3; ++st) {
                uint4 Ah = AHq[(st * 16 + step) * 32];
                uint4 Al = ALq[(st * 16 + step) * 32];
                #pragma unroll
                for (int nt = 0; nt < 4; ++nt) {
                    MMA(D[st][nt], Ah.x, Ah.y, Ah.z, Ah.w, qb[nt].x, qb[nt].y);
                    MMA(D[st][nt], Ah.x, Ah.y, Ah.z, Ah.w, qb[nt].z, qb[nt].w);
                    MMA(D[st][nt], Al.x, Al.y, Al.z, Al.w, qb[nt].x, qb[nt].y);
                }
            }
        }
        __syncthreads();   // all warps done reading A planes before rewrite

        // ---- jet epilogue ----
        if (l == 1) {
            #pragma unroll
            for (int a = 0; a < 2; ++a)
                #pragma unroll
                for (int c = 0; c < 3; ++c) ps[a][c] = 0.f;
        }
        #pragma unroll
        for (int nt = 0; nt < 4; ++nt) {
            const int ntg = (w & 1) * 4 + nt;
            const int u0 = (w >> 1) * 64 + ntg * 8 + (tid3 << 1);
            float2 bb  = *(const float2*)(biasSm + (l ? 256 : 0) + u0);
            float2 w4v = *(const float2*)(w4Sm + u0);
            float av[4], a1v[4], a2v[4];
            #pragma unroll
            for (int p_ = 0; p_ < 4; ++p_) {
                float z  = D[0][nt][p_] + ((p_ & 1) ? bb.y : bb.x);
                float z1 = D[1][nt][p_];
                float z2 = D[2][nt][p_];
                float a, s2;
                tanh_d(z, a, s2);
                av[p_]  = a;
                a1v[p_] = s2 * z1;
                a2v[p_] = s2 * z2 - 2.f * a * a1v[p_] * z1;
            }
            if (l == 0) {
                const int pi = u0 >> 1;                // k-pair index
                const int step_t = pi >> 3, o = pi & 7;
                const int wsel = (o & 4) ? 2 : 0;
                const int lane_t = (g4 << 2) | (o & 3);
                uint32_t hA, lA, hB, lB;
                #pragma unroll
                for (int st = 0; st < 3; ++st) {
                    const float* v = (st == 0) ? av : (st == 1) ? a1v : a2v;
                    pk2(v[0], v[1], hA, lA);      // row g4
                    pk2(v[2], v[3], hB, lB);      // row g4+8
                    const int base = ((st * 16 + step_t) * 32 + lane_t) * 4 + wsel;
                    *(uint2*)(AH + base) = make_uint2(hA, hB);
                    *(uint2*)(AL + base) = make_uint2(lA, lB);
                }
            } else {
                #pragma unroll
                for (int p_ = 0; p_ < 4; ++p_) {
                    float wv = (p_ & 1) ? w4v.y : w4v.x;
                    int rh = p_ >> 1;
                    ps[rh][0] += av[p_]  * wv;
                    ps[rh][1] += a1v[p_] * wv;
                    ps[rh][2] += a2v[p_] * wv;
                }
            }
        }
        if (l == 0) {
            __syncthreads();           // A planes fully rewritten before layer-2
        } else {
            #pragma unroll
            for (int rh = 0; rh < 2; ++rh)
                #pragma unroll
                for (int st = 0; st < 3; ++st) {
                    float v = ps[rh][st];
                    v += __shfl_xor_sync(0xffffffffu, v, 1);
                    v += __shfl_xor_sync(0xffffffffu, v, 2);
                    if (tid3 == 0)
                        atomicAdd(&outSm[st * 16 + g4 + rh * 8], v);
                }
        }
    }

    __syncthreads();
    if (t < 48) {
        int st = t >> 4, s = t & 15;
        float v = outSm[t] + (st == 0 ? b4[0] : 0.f);
        out[st * B + bs + s] = v;
    }
}

extern "C" void kernel_launch(void* const* d_in, const int* in_sizes, int n_in,
                              void* d_out, int out_size) {
    const float* x  = (const float*)d_in[0];
    const float* W1 = (const float*)d_in[1];
    const float* b1 = (const float*)d_in[2];
    const float* W2 = (const float*)d_in[3];
    const float* b2 = (const float*)d_in[4];
    const float* W3 = (const float*)d_in[5];
    const float* b3 = (const float*)d_in[6];
    const float* W4 = (const float*)d_in[7];
    const float* b4 = (const float*)d_in[8];
    float* out = (float*)d_out;
    const int B = in_sizes[0] / 2;

    prep_w<<<32, 128>>>(W2, W3);

    cudaFuncSetAttribute(pinn_mma_kernel,
                         cudaFuncAttributeMaxDynamicSharedMemorySize, SM_TOT);
    pinn_mma_kernel<<<B / 16, 256, SM_TOT>>>(x, W1, b1, b2, b3, W4, b4, out, B);
}